// round 17
// baseline (speedup 1.0000x reference)
#include <cuda_runtime.h>
#include <cuda_fp16.h>
#include <mma.h>
#include <math.h>
#include <cstdint>

using namespace nvcuda;

#define NN    50000
#define EE    800000
#define ET    (EE + NN)
#define IND   256
#define HID   32
#define HEADS 4
#define HH    (HEADS * HID)      // 128
#define SLOPE 0.2f

// gemm1 tiling (fp16 operands, m16n16k16)
#define BM    128
#define BK    32
#define XSTRH (BK + 8)           // 40 halves
#define WSTRH (HH + 8)           // 136 halves
#define OSTR  (HH + 4)           // 132 floats
#define GEMM1_SMEM (BM * OSTR * 4)   // 67584 B

#define SCAN_B 196               // ceil(50000/256)

// ---------------- scratch ----------------
__device__ __half d_h1h[NN * HH];   // fp16 h1 for gather
__device__ float d_as1[NN * HEADS];
__device__ float d_ad1[NN * HEADS];

__device__ __half d_h2h[NN * HID];  // fp16 h2 for gather
__device__ float d_as2[NN];
__device__ float d_ad2[NN];

// CSR scratch: [0,NN) = histogram counts, [NN,2NN) = scatter cursors
__device__ int d_cnt   [2 * NN];
__device__ int d_rowptr[NN + 1];
__device__ int d_esrc  [ET];
__device__ int d_bsum  [256];

// ---------------- helpers ----------------
__device__ __forceinline__ float lrelu(float v) { return v > 0.0f ? v : SLOPE * v; }
__device__ __forceinline__ float eluf (float v) { return v > 0.0f ? v : __expf(v) - 1.0f; }

// ---------------- CSR build ----------------
__global__ void k_hist(const int* __restrict__ ei) {
    int e = blockIdx.x * blockDim.x + threadIdx.x;
    if (e < EE) atomicAdd(&d_cnt[ei[EE + e]], 1);
}

__global__ void k_scanA() {
    __shared__ int sh[256];
    int t = threadIdx.x;
    int idx = blockIdx.x * 256 + t;
    int c = (idx < NN) ? (d_cnt[idx] + 1) : 0;   // +1: self loop
    sh[t] = c;
    __syncthreads();
#pragma unroll
    for (int off = 1; off < 256; off <<= 1) {
        int v = (t >= off) ? sh[t - off] : 0;
        __syncthreads();
        sh[t] += v;
        __syncthreads();
    }
    if (idx < NN) d_rowptr[idx] = sh[t] - c;
    if (t == 255) d_bsum[blockIdx.x] = sh[255];
}

__global__ void k_scanBC() {
    __shared__ int sh[256];
    int t = threadIdx.x;
    int b = blockIdx.x;
    sh[t] = (t < b) ? d_bsum[t] : 0;
    __syncthreads();
#pragma unroll
    for (int off = 128; off; off >>= 1) {
        if (t < off) sh[t] += sh[t + off];
        __syncthreads();
    }
    int pref = sh[0];
    int idx = b * 256 + t;
    if (idx < NN) {
        d_rowptr[idx] += pref;
        d_cnt[idx] = 0;
        d_cnt[NN + idx] = 0;
    }
    if (idx == 0) d_rowptr[NN] = ET;
}

__global__ void k_scatter(const int* __restrict__ ei) {
    int id = blockIdx.x * blockDim.x + threadIdx.x;
    if (id >= ET) return;
    int s, d;
    if (id < EE) { s = ei[id]; d = ei[EE + id]; }
    else         { s = id - EE; d = id - EE; }
    int pos = d_rowptr[d] + atomicAdd(&d_cnt[NN + d], 1);
    d_esrc[pos] = s;
}

// ---------------- layer 1: FP16 wmma GEMM (m16n16k16) + attention scalars ----------------
__global__ void __launch_bounds__(256) k_gemm1(
        const float* __restrict__ x, const float* __restrict__ W,
        const float* __restrict__ att_s, const float* __restrict__ att_d) {
    extern __shared__ float smem[];
    __half* xs = (__half*)smem;                       // [BM][XSTRH]
    __half* ws = (__half*)(smem + BM * XSTRH / 2);    // [BK][WSTRH]
    float*  os = smem;                                // epilogue reuse

    int tid  = threadIdx.x;
    int wid  = tid >> 5, lane = tid & 31;
    int n0   = blockIdx.x * BM;
    int wm   = wid & 3;
    int wn   = wid >> 2;

    wmma::fragment<wmma::accumulator, 16, 16, 16, float> c[2][4];
#pragma unroll
    for (int i = 0; i < 2; i++)
#pragma unroll
        for (int j = 0; j < 4; j++) wmma::fill_fragment(c[i][j], 0.0f);

    for (int k0 = 0; k0 < IND; k0 += BK) {
#pragma unroll
        for (int it = 0; it < 4; it++) {
            int i   = tid + it * 256;
            int row = i >> 3, kq = i & 7;
            int n   = n0 + row;
            float4 v = make_float4(0.f, 0.f, 0.f, 0.f);
            if (n < NN) v = *(const float4*)&x[(size_t)n * IND + k0 + kq * 4];
            *(__half2*)&xs[row * XSTRH + kq * 4 + 0] = __floats2half2_rn(v.x, v.y);
            *(__half2*)&xs[row * XSTRH + kq * 4 + 2] = __floats2half2_rn(v.z, v.w);
        }
#pragma unroll
        for (int it = 0; it < 4; it++) {
            int i  = tid + it * 256;
            int k  = i >> 5, nq = i & 31;
            float4 v = *(const float4*)&W[(size_t)(k0 + k) * HH + nq * 4];
            *(__half2*)&ws[k * WSTRH + nq * 4 + 0] = __floats2half2_rn(v.x, v.y);
            *(__half2*)&ws[k * WSTRH + nq * 4 + 2] = __floats2half2_rn(v.z, v.w);
        }
        __syncthreads();

#pragma unroll
        for (int kk = 0; kk < BK; kk += 16) {
            wmma::fragment<wmma::matrix_a, 16, 16, 16, __half, wmma::row_major> a[2];
            wmma::fragment<wmma::matrix_b, 16, 16, 16, __half, wmma::row_major> b[4];
#pragma unroll
            for (int i = 0; i < 2; i++)
                wmma::load_matrix_sync(a[i], &xs[(wm * 32 + i * 16) * XSTRH + kk], XSTRH);
#pragma unroll
            for (int j = 0; j < 4; j++)
                wmma::load_matrix_sync(b[j], &ws[kk * WSTRH + wn * 64 + j * 16], WSTRH);
#pragma unroll
            for (int i = 0; i < 2; i++)
#pragma unroll
                for (int j = 0; j < 4; j++)
                    wmma::mma_sync(c[i][j], a[i], b[j], c[i][j]);
        }
        __syncthreads();
    }

#pragma unroll
    for (int i = 0; i < 2; i++)
#pragma unroll
        for (int j = 0; j < 4; j++)
            wmma::store_matrix_sync(&os[(wm * 32 + i * 16) * OSTR + wn * 64 + j * 16],
                                    c[i][j], OSTR, wmma::mem_row_major);
    __syncthreads();

    int head = wid & 3;
    int rofs = wid >> 2;
    float es = att_s[head * HID + lane];
    float ed = att_d[head * HID + lane];
#pragma unroll 4
    for (int r2 = 0; r2 < BM; r2 += 2) {
        int r = r2 + rofs;
        int n = n0 + r;
        if (n >= NN) continue;
        float v = os[r * OSTR + head * 32 + lane];
        d_h1h[(size_t)n * HH + head * 32 + lane] = __float2half_rn(v);
        float s = v * es, t = v * ed;
#pragma unroll
        for (int o = 16; o; o >>= 1) {
            s += __shfl_xor_sync(0xffffffffu, s, o);
            t += __shfl_xor_sync(0xffffffffu, t, o);
        }
        if (lane == 0) { d_as1[n * HEADS + head] = s; d_ad1[n * HEADS + head] = t; }
    }
}

// ---------------- FUSED: layer-1 gather + layer-2 GEMM ----------------
// 8-edge chunks: lane j precomputes p(edge j&7, head j>>3); inner loop
// distributes via computed-source shuffle. One exp + one as1 LDG per lane per 8 edges.
__global__ void __launch_bounds__(256) k_fuse(
        const float* __restrict__ b1, const float* __restrict__ W2,
        const float* __restrict__ att_s2, const float* __restrict__ att_d2) {
    __shared__ float Ws[HH * HID];    // 16 KB
    __shared__ float xs[32][HH];      // 16 KB
    int tid = threadIdx.x;
    int w = tid >> 5, lane = tid & 31;
    int n0 = blockIdx.x * 32;

    for (int t = tid; t < HH * HID; t += 256) Ws[t] = W2[t];

    int h   = lane >> 3;              // consumer head (cols lane*4..lane*4+3)
    int el  = lane & 7;               // producer edge slot within chunk
    int psrc = lane & 24;             // h*8: base lane holding my head's p values
    float4 bb = *(const float4*)&b1[lane * 4];

#pragma unroll
    for (int r = 0; r < 4; r++) {
        int row = w * 4 + r;
        int n = n0 + row;
        if (n >= NN) break;

        int start = d_rowptr[n], end = d_rowptr[n + 1];
        float adh = d_ad1[n * 4 + h];     // my head's dst score

        float4 acc = make_float4(0.f, 0.f, 0.f, 0.f);
        float  den = 0.f;

        for (int base = start; base < end; base += 8) {
            int m = min(8, end - base);
            // lane j: edge (j&7), head (j>>3)
            int   sj = (el < m) ? __ldg(&d_esrc[base + el]) : 0;
            float pj = 0.f;
            if (el < m)
                pj = __expf(lrelu(__ldg(&d_as1[sj * 4 + h]) + adh));
#pragma unroll 4
            for (int i = 0; i < m; i++) {
                int   s = __shfl_sync(0xffffffffu, sj, i);          // lane i holds edge i's src
                float p = __shfl_sync(0xffffffffu, pj, psrc + i);   // lane h*8+i holds p(i,h)
                uint2 raw = *(const uint2*)&d_h1h[(size_t)s * HH + lane * 4];
                float2 f01 = __half22float2(*(__half2*)&raw.x);
                float2 f23 = __half22float2(*(__half2*)&raw.y);
                den  += p;
                acc.x = fmaf(p, f01.x, acc.x);
                acc.y = fmaf(p, f01.y, acc.y);
                acc.z = fmaf(p, f23.x, acc.z);
                acc.w = fmaf(p, f23.y, acc.w);
            }
        }

        float inv = 1.0f / den;
        acc.x = eluf(acc.x * inv + bb.x);
        acc.y = eluf(acc.y * inv + bb.y);
        acc.z = eluf(acc.z * inv + bb.z);
        acc.w = eluf(acc.w * inv + bb.w);
        *(float4*)&xs[row][lane * 4] = acc;
    }
    __syncthreads();

    // gemm2 phase
    float as_l = att_s2[lane], ad_l = att_d2[lane];
#pragma unroll
    for (int r = 0; r < 4; r++) {
        int row = w * 4 + r;
        int n = n0 + row;
        if (n >= NN) break;
        float acc = 0.0f;
#pragma unroll 8
        for (int k = 0; k < HH; k += 4) {
            float4 xv = *(const float4*)&xs[row][k];
            acc += xv.x * Ws[(k + 0) * HID + lane];
            acc += xv.y * Ws[(k + 1) * HID + lane];
            acc += xv.z * Ws[(k + 2) * HID + lane];
            acc += xv.w * Ws[(k + 3) * HID + lane];
        }
        d_h2h[n * HID + lane] = __float2half_rn(acc);
        float s = acc * as_l, t = acc * ad_l;
#pragma unroll
        for (int o = 16; o; o >>= 1) {
            s += __shfl_xor_sync(0xffffffffu, s, o);
            t += __shfl_xor_sync(0xffffffffu, t, o);
        }
        if (lane == 0) { d_as2[n] = s; d_ad2[n] = t; }
    }
}

// ---------------- layer 2: CSR gather + bias/ELU + classifier ----------------
// p precomputed once per lane per 32-edge chunk (single head).
__global__ void k_gather2(const float* __restrict__ b2, const float* __restrict__ lw,
                          const float* __restrict__ lb, float* __restrict__ out) {
    int gid  = blockIdx.x * blockDim.x + threadIdx.x;
    int n    = gid >> 5;
    if (n >= NN) return;
    int lane = gid & 31;

    int start = d_rowptr[n], end = d_rowptr[n + 1];
    float ad = d_ad2[n];

    float acc = 0.f, den = 0.f;
    for (int base = start; base < end; base += 32) {
        int m   = min(32, end - base);
        int   myS = (lane < m) ? __ldg(&d_esrc[base + lane]) : 0;
        float myP = 0.f;
        if (lane < m)
            myP = __expf(lrelu(__ldg(&d_as2[myS]) + ad));
#pragma unroll 4
        for (int i = 0; i < m; i++) {
            int   s = __shfl_sync(0xffffffffu, myS, i);
            float p = __shfl_sync(0xffffffffu, myP, i);
            den += p;
            acc = fmaf(p, __half2float(d_h2h[s * HID + lane]), acc);
        }
    }

    float v = eluf(acc / den + b2[lane]);
    float o0 = v * lw[lane * 2 + 0];
    float o1 = v * lw[lane * 2 + 1];
#pragma unroll
    for (int o = 16; o; o >>= 1) {
        o0 += __shfl_xor_sync(0xffffffffu, o0, o);
        o1 += __shfl_xor_sync(0xffffffffu, o1, o);
    }
    if (lane == 0) { out[n * 2 + 0] = o0 + lb[0]; out[n * 2 + 1] = o1 + lb[1]; }
}

// ---------------- launch ----------------
extern "C" void kernel_launch(void* const* d_in, const int* in_sizes, int n_in,
                              void* d_out, int out_size) {
    const float* x        = (const float*)d_in[0];
    const int*   ei       = (const int*)  d_in[1];
    const float* W1       = (const float*)d_in[2];
    const float* att_src1 = (const float*)d_in[3];
    const float* att_dst1 = (const float*)d_in[4];
    const float* b1       = (const float*)d_in[5];
    const float* W2       = (const float*)d_in[6];
    const float* att_src2 = (const float*)d_in[7];
    const float* att_dst2 = (const float*)d_in[8];
    const float* b2       = (const float*)d_in[9];
    const float* lin_w    = (const float*)d_in[10];
    const float* lin_b    = (const float*)d_in[11];
    float* out = (float*)d_out;
    (void)in_sizes; (void)n_in; (void)out_size;

    const int GW = (NN * 32 + 255) / 256;

    static cudaStream_t s2 = nullptr;
    static cudaEvent_t evFork = nullptr, evJoin = nullptr;
    static bool inited = false;
    if (!inited) {
        cudaFuncSetAttribute(k_gemm1, cudaFuncAttributeMaxDynamicSharedMemorySize, GEMM1_SMEM);
        cudaStreamCreateWithFlags(&s2, cudaStreamNonBlocking);
        cudaEventCreateWithFlags(&evFork, cudaEventDisableTiming);
        cudaEventCreateWithFlags(&evJoin, cudaEventDisableTiming);
        inited = true;
    }

    // fork: gemm1 on side stream
    cudaEventRecord(evFork, 0);
    cudaStreamWaitEvent(s2, evFork, 0);
    k_gemm1<<<(NN + BM - 1) / BM, 256, GEMM1_SMEM, s2>>>(x, W1, att_src1, att_dst1);
    cudaEventRecord(evJoin, s2);

    // CSR build on stream 0
    k_hist<<<(EE + 255) / 256, 256>>>(ei);
    k_scanA<<<SCAN_B, 256>>>();
    k_scanBC<<<SCAN_B, 256>>>();
    k_scatter<<<(ET + 255) / 256, 256>>>(ei);

    // join
    cudaStreamWaitEvent(0, evJoin, 0);
    k_fuse<<<(NN + 31) / 32, 256>>>(b1, W2, att_src2, att_dst2);

    k_gather2<<<GW, 256>>>(b2, lin_w, lin_b, out);
}